// round 3
// baseline (speedup 1.0000x reference)
#include <cuda_runtime.h>

#define NN 100000
#define NE 3200000
#define HD 128
#define HD2 256
#define NL 4
#define NG 512
#define SCAN_NB 98   // ceil(100000/1024)

// ---------------- device scratch (allocation-free rule: __device__ globals) ---
__device__ float g_h[NN * HD];      // node features          (51.2 MB)
__device__ float g_z[NN * HD];      // (1+eps)*h + agg        (51.2 MB)
__device__ float g_u[NN * HD2];     // hidden after MLP fc1   (102.4 MB)
__device__ int   g_deg[NN];
__device__ int   g_inc[NN];
__device__ int   g_rowptr[NN + 1];
__device__ int   g_cursor[NN];
__device__ int   g_col[NE];
__device__ int   g_bsum[SCAN_NB];
__device__ int   g_boff[SCAN_NB];

// ---------------- CSR build --------------------------------------------------
__global__ void k_zero_deg() {
    int i = blockIdx.x * blockDim.x + threadIdx.x;
    if (i < NN) g_deg[i] = 0;
}

__global__ void k_hist(const int* __restrict__ ei) {
    int e = blockIdx.x * blockDim.x + threadIdx.x;
    if (e < NE) {
        int d = ei[NE + e];    // dst row of edge_index (int32)
        atomicAdd(&g_deg[d], 1);
    }
}

__global__ void k_scan1() {
    __shared__ int s[1024];
    int tid = threadIdx.x;
    int i = blockIdx.x * 1024 + tid;
    int v = (i < NN) ? g_deg[i] : 0;
    s[tid] = v;
    __syncthreads();
    for (int off = 1; off < 1024; off <<= 1) {
        int t = (tid >= off) ? s[tid - off] : 0;
        __syncthreads();
        s[tid] += t;
        __syncthreads();
    }
    if (i < NN) g_inc[i] = s[tid];
    if (tid == 1023) g_bsum[blockIdx.x] = s[1023];
}

__global__ void k_scan2() {
    __shared__ int s[128];
    int tid = threadIdx.x;
    int v = (tid < SCAN_NB) ? g_bsum[tid] : 0;
    s[tid] = v;
    __syncthreads();
    for (int off = 1; off < 128; off <<= 1) {
        int t = (tid >= off) ? s[tid - off] : 0;
        __syncthreads();
        s[tid] += t;
        __syncthreads();
    }
    if (tid < SCAN_NB) g_boff[tid] = s[tid] - v;   // exclusive block offset
}

__global__ void k_finalize() {
    int i = blockIdx.x * blockDim.x + threadIdx.x;
    if (i >= NN) return;
    int ex = g_inc[i] - g_deg[i] + g_boff[i >> 10];
    g_rowptr[i] = ex;
    g_cursor[i] = ex;
    if (i == NN - 1) g_rowptr[NN] = ex + g_deg[i];
}

__global__ void k_scatter(const int* __restrict__ ei) {
    int e = blockIdx.x * blockDim.x + threadIdx.x;
    if (e < NE) {
        int d = ei[NE + e];
        int p = atomicAdd(&g_cursor[d], 1);
        g_col[p] = ei[e];
    }
}

// ---------------- atom embedding: h = x @ Wemb + bemb ------------------------
__global__ void k_embed(const float* __restrict__ x, const float* __restrict__ W,
                        const float* __restrict__ b) {
    int idx = blockIdx.x * blockDim.x + threadIdx.x;
    if (idx >= NN * HD) return;
    int n = idx >> 7, c = idx & 127;
    const float* xr = x + n * 9;
    float acc = b[c];
#pragma unroll
    for (int k = 0; k < 9; k++) acc = fmaf(xr[k], W[k * HD + c], acc);
    g_h[idx] = acc;
}

// ---------------- GIN aggregation: z = (1+eps)*h + sum_{nbr} h ---------------
__global__ void k_agg(const float* __restrict__ eps, int l) {
    int wid = (blockIdx.x * blockDim.x + threadIdx.x) >> 5;
    if (wid >= NN) return;
    int lane = threadIdx.x & 31;
    const float4* h4 = (const float4*)g_h;
    float sc = 1.0f + eps[l];
    float4 a = h4[wid * 32 + lane];
    a.x *= sc; a.y *= sc; a.z *= sc; a.w *= sc;
    int j = g_rowptr[wid], e = g_rowptr[wid + 1];
    for (; j + 3 < e; j += 4) {
        int m0 = g_col[j], m1 = g_col[j + 1], m2 = g_col[j + 2], m3 = g_col[j + 3];
        float4 v0 = h4[m0 * 32 + lane];
        float4 v1 = h4[m1 * 32 + lane];
        float4 v2 = h4[m2 * 32 + lane];
        float4 v3 = h4[m3 * 32 + lane];
        a.x += v0.x + v1.x + v2.x + v3.x;
        a.y += v0.y + v1.y + v2.y + v3.y;
        a.z += v0.z + v1.z + v2.z + v3.z;
        a.w += v0.w + v1.w + v2.w + v3.w;
    }
    for (; j < e; j++) {
        int m = g_col[j];
        float4 v = h4[m * 32 + lane];
        a.x += v.x; a.y += v.y; a.z += v.z; a.w += v.w;
    }
    ((float4*)g_z)[wid * 32 + lane] = a;
}

// ---------------- fused GEMM + BN + ReLU --------------------------------------
// mode 0:  u = relu(A1*(z @ W1) + C1)   [NN,128] @ [128,256]
// mode 1:  h = relu(A2*(u @ W2) + C2)   [NN,256] @ [256,128]
// Tile: 128 rows x 128 cols per CTA (blockIdx.y = 128-col chunk),
// Ktile = 32, static smem 32 KB, 256 threads, 8x8 register blocking.
__global__ void __launch_bounds__(256)
k_gemm(int mode, const float* __restrict__ W, const float* __restrict__ b,
       const float* __restrict__ gm, const float* __restrict__ bt,
       const float* __restrict__ mn, const float* __restrict__ vr) {
    const float* in  = mode ? g_u : g_z;
    float*       out = mode ? g_h : g_u;
    const int Kdim = mode ? HD2 : HD;
    const int Nout = mode ? HD : HD2;

    __shared__ float As[32][128];   // k-major A tile
    __shared__ float Bs[32][128];   // k-major B tile

    int tid = threadIdx.x;
    int row0  = blockIdx.x * 128;
    int ncol0 = blockIdx.y * 128;

    int ty = tid >> 4, tx = tid & 15;
    int m0 = ty * 8, n0 = tx * 8;

    float acc[8][8];
#pragma unroll
    for (int ii = 0; ii < 8; ii++)
#pragma unroll
        for (int jj = 0; jj < 8; jj++) acc[ii][jj] = 0.f;

    int ar = tid >> 1, ac = (tid & 1) * 16;       // A fill: row ar, 16 k-cols
    int bkr = tid >> 3, bc = (tid & 7) * 16;      // B fill: k-row bkr, 16 n-cols

    int ktiles = Kdim >> 5;
    for (int kt = 0; kt < ktiles; kt++) {
        int arow = row0 + ar;
        const float* src = in + arow * Kdim + kt * 32 + ac;
#pragma unroll
        for (int q = 0; q < 4; q++) {
            float4 v = (arow < NN) ? *(const float4*)(src + q * 4)
                                   : make_float4(0.f, 0.f, 0.f, 0.f);
            As[ac + q * 4 + 0][ar] = v.x;
            As[ac + q * 4 + 1][ar] = v.y;
            As[ac + q * 4 + 2][ar] = v.z;
            As[ac + q * 4 + 3][ar] = v.w;
        }
        const float* wsrc = W + (kt * 32 + bkr) * Nout + ncol0 + bc;
#pragma unroll
        for (int q = 0; q < 4; q++)
            *(float4*)&Bs[bkr][bc + q * 4] = *(const float4*)(wsrc + q * 4);
        __syncthreads();

#pragma unroll
        for (int k = 0; k < 32; k++) {
            float4 a0 = *(const float4*)&As[k][m0];
            float4 a1 = *(const float4*)&As[k][m0 + 4];
            float4 b0 = *(const float4*)&Bs[k][n0];
            float4 b1 = *(const float4*)&Bs[k][n0 + 4];
            float av[8] = {a0.x, a0.y, a0.z, a0.w, a1.x, a1.y, a1.z, a1.w};
            float bv[8] = {b0.x, b0.y, b0.z, b0.w, b1.x, b1.y, b1.z, b1.w};
#pragma unroll
            for (int ii = 0; ii < 8; ii++)
#pragma unroll
                for (int jj = 0; jj < 8; jj++)
                    acc[ii][jj] = fmaf(av[ii], bv[jj], acc[ii][jj]);
        }
        __syncthreads();
    }

    // folded BN epilogue: y = relu(acc * Ac + Cc)
    float Ac[8], Cc[8];
#pragma unroll
    for (int jj = 0; jj < 8; jj++) {
        int c = ncol0 + n0 + jj;
        float a = gm[c] * rsqrtf(vr[c] + 1e-5f);
        Ac[jj] = a;
        Cc[jj] = fmaf(a, b[c] - mn[c], bt[c]);
    }
#pragma unroll
    for (int ii = 0; ii < 8; ii++) {
        int row = row0 + m0 + ii;
        if (row < NN) {
#pragma unroll
            for (int jj = 0; jj < 8; jj += 4) {
                float4 o;
                o.x = fmaxf(fmaf(acc[ii][jj + 0], Ac[jj + 0], Cc[jj + 0]), 0.f);
                o.y = fmaxf(fmaf(acc[ii][jj + 1], Ac[jj + 1], Cc[jj + 1]), 0.f);
                o.z = fmaxf(fmaf(acc[ii][jj + 2], Ac[jj + 2], Cc[jj + 2]), 0.f);
                o.w = fmaxf(fmaf(acc[ii][jj + 3], Ac[jj + 3], Cc[jj + 3]), 0.f);
                *(float4*)&out[row * Nout + ncol0 + n0 + jj] = o;
            }
        }
    }
}

// ---------------- global mean pool (batch sorted -> binary search bounds) ----
__global__ void k_pool(const int* __restrict__ batch, float* __restrict__ out) {
    int g = blockIdx.x;
    int c = threadIdx.x;
    int lo = 0, hi = NN;
    while (lo < hi) { int mid = (lo + hi) >> 1; if (batch[mid] < g) lo = mid + 1; else hi = mid; }
    int start = lo;
    lo = start; hi = NN;
    while (lo < hi) { int mid = (lo + hi) >> 1; if (batch[mid] < g + 1) lo = mid + 1; else hi = mid; }
    int end = lo;
    float acc = 0.f;
    int n = start;
    for (; n + 3 < end; n += 4) {
        acc += g_h[(n + 0) * HD + c];
        acc += g_h[(n + 1) * HD + c];
        acc += g_h[(n + 2) * HD + c];
        acc += g_h[(n + 3) * HD + c];
    }
    for (; n < end; n++) acc += g_h[n * HD + c];
    float cnt = (float)(end - start);
    out[g * HD + c] = acc / fmaxf(cnt, 1.f);
}

// ---------------- launch ------------------------------------------------------
extern "C" void kernel_launch(void* const* d_in, const int* in_sizes, int n_in,
                              void* d_out, int out_size) {
    const float* x    = (const float*)d_in[0];
    const int*   ei   = (const int*)d_in[1];     // int32 (JAX x64 disabled)
    const int*   bat  = (const int*)d_in[2];     // int32
    const float* Wemb = (const float*)d_in[3];
    const float* bemb = (const float*)d_in[4];
    const float* eps  = (const float*)d_in[5];
    const float* W1   = (const float*)d_in[6];
    const float* b1   = (const float*)d_in[7];
    const float* g1   = (const float*)d_in[8];
    const float* be1  = (const float*)d_in[9];
    const float* m1   = (const float*)d_in[10];
    const float* v1   = (const float*)d_in[11];
    const float* W2   = (const float*)d_in[12];
    const float* b2   = (const float*)d_in[13];
    const float* g2   = (const float*)d_in[14];
    const float* be2  = (const float*)d_in[15];
    const float* m2   = (const float*)d_in[16];
    const float* v2   = (const float*)d_in[17];
    float* out = (float*)d_out;

    const int MT = (NN + 127) / 128;   // 782 row tiles

    // CSR build (once per launch)
    k_zero_deg<<<(NN + 255) / 256, 256>>>();
    k_hist<<<(NE + 255) / 256, 256>>>(ei);
    k_scan1<<<SCAN_NB, 1024>>>();
    k_scan2<<<1, 128>>>();
    k_finalize<<<(NN + 255) / 256, 256>>>();
    k_scatter<<<(NE + 255) / 256, 256>>>(ei);

    // embedding
    k_embed<<<(NN * HD + 255) / 256, 256>>>(x, Wemb, bemb);

    // 4 GIN layers
    for (int l = 0; l < NL; l++) {
        k_agg<<<(NN + 7) / 8, 256>>>(eps, l);
        k_gemm<<<dim3(MT, 2), 256>>>(0, W1 + (size_t)l * HD * HD2, b1 + l * HD2,
                                     g1 + l * HD2, be1 + l * HD2,
                                     m1 + l * HD2, v1 + l * HD2);
        k_gemm<<<dim3(MT, 1), 256>>>(1, W2 + (size_t)l * HD2 * HD, b2 + l * HD,
                                     g2 + l * HD, be2 + l * HD,
                                     m2 + l * HD, v2 + l * HD);
    }

    // pool
    k_pool<<<NG, 128>>>(bat, out);
}

// round 5
// speedup vs baseline: 1.6455x; 1.6455x over previous
#include <cuda_runtime.h>
#include <cuda_bf16.h>
#include <cstdint>

#define NN 100000
#define NE 3200000
#define HD 128
#define HD2 256
#define NL 4
#define NG 512
#define SCAN_NB 98   // ceil(100000/1024)

// ---------------- PTX helpers (all plain-sm_103 legal) -------------------------
__device__ __forceinline__ uint32_t smem_u32(const void* p) {
    uint32_t a;
    asm("{ .reg .u64 t; cvta.to.shared.u64 t, %1; cvt.u32.u64 %0, t; }" : "=r"(a) : "l"(p));
    return a;
}
#define LDSM4(r, a) \
    asm volatile("ldmatrix.sync.aligned.m8n8.x4.shared.b16 {%0,%1,%2,%3}, [%4];" \
        : "=r"((r)[0]), "=r"((r)[1]), "=r"((r)[2]), "=r"((r)[3]) : "r"(a))
#define MMA16816(d, a, b0, b1) \
    asm volatile("mma.sync.aligned.m16n8k16.row.col.f32.bf16.bf16.f32 " \
        "{%0,%1,%2,%3}, {%4,%5,%6,%7}, {%8,%9}, {%0,%1,%2,%3};" \
        : "+f"((d)[0]), "+f"((d)[1]), "+f"((d)[2]), "+f"((d)[3]) \
        : "r"((a)[0]), "r"((a)[1]), "r"((a)[2]), "r"((a)[3]), "r"(b0), "r"(b1))

// ---------------- device scratch ----------------------------------------------
__device__ __align__(16) float          g_h[NN * HD];            // fp32 node features
__device__ __align__(16) __nv_bfloat16  g_zhi[NN * HD];
__device__ __align__(16) __nv_bfloat16  g_zlo[NN * HD];
__device__ __align__(16) __nv_bfloat16  g_uhi[(size_t)NN * HD2];
__device__ __align__(16) __nv_bfloat16  g_ulo[(size_t)NN * HD2];
__device__ __align__(16) __nv_bfloat16  g_B1w[NL * 2 * HD2 * HD];   // [l][hi|lo][n=256][k=128]
__device__ __align__(16) __nv_bfloat16  g_B2w[NL * 2 * HD * HD2];   // [l][hi|lo][n=128][k=256]
__device__ int g_deg[NN], g_inc[NN], g_rowptr[NN + 1], g_cursor[NN], g_col[NE];
__device__ int g_bsum[SCAN_NB], g_boff[SCAN_NB];

// ---------------- CSR build ---------------------------------------------------
__global__ void k_zero_deg() {
    int i = blockIdx.x * blockDim.x + threadIdx.x;
    if (i < NN) g_deg[i] = 0;
}
__global__ void k_hist(const int* __restrict__ ei) {
    int e = blockIdx.x * blockDim.x + threadIdx.x;
    if (e < NE) atomicAdd(&g_deg[ei[NE + e]], 1);
}
__global__ void k_scan1() {
    __shared__ int s[1024];
    int tid = threadIdx.x, i = blockIdx.x * 1024 + tid;
    int v = (i < NN) ? g_deg[i] : 0;
    s[tid] = v; __syncthreads();
    for (int off = 1; off < 1024; off <<= 1) {
        int t = (tid >= off) ? s[tid - off] : 0;
        __syncthreads(); s[tid] += t; __syncthreads();
    }
    if (i < NN) g_inc[i] = s[tid];
    if (tid == 1023) g_bsum[blockIdx.x] = s[1023];
}
__global__ void k_scan2() {
    __shared__ int s[128];
    int tid = threadIdx.x;
    int v = (tid < SCAN_NB) ? g_bsum[tid] : 0;
    s[tid] = v; __syncthreads();
    for (int off = 1; off < 128; off <<= 1) {
        int t = (tid >= off) ? s[tid - off] : 0;
        __syncthreads(); s[tid] += t; __syncthreads();
    }
    if (tid < SCAN_NB) g_boff[tid] = s[tid] - v;
}
__global__ void k_finalize() {
    int i = blockIdx.x * blockDim.x + threadIdx.x;
    if (i >= NN) return;
    int ex = g_inc[i] - g_deg[i] + g_boff[i >> 10];
    g_rowptr[i] = ex; g_cursor[i] = ex;
    if (i == NN - 1) g_rowptr[NN] = ex + g_deg[i];
}
__global__ void k_scatter(const int* __restrict__ ei) {
    int e = blockIdx.x * blockDim.x + threadIdx.x;
    if (e < NE) {
        int p = atomicAdd(&g_cursor[ei[NE + e]], 1);
        g_col[p] = ei[e];
    }
}

// ---------------- weight packing: [n][k] row-major bf16 hi/lo ------------------
__global__ void k_packW1(const float* __restrict__ W1) {
    int idx = blockIdx.x * blockDim.x + threadIdx.x;     // NL*256*128
    if (idx >= NL * HD2 * HD) return;
    int l = idx / (HD2 * HD), rem = idx % (HD2 * HD);
    int n = rem / HD, k = rem % HD;
    float w = W1[((size_t)l * HD + k) * HD2 + n];
    __nv_bfloat16 h = __float2bfloat16(w);
    __nv_bfloat16 lo = __float2bfloat16(w - __bfloat162float(h));
    size_t base = (size_t)l * 2 * HD2 * HD;
    g_B1w[base + (size_t)n * HD + k] = h;
    g_B1w[base + (size_t)HD2 * HD + (size_t)n * HD + k] = lo;
}
__global__ void k_packW2(const float* __restrict__ W2) {
    int idx = blockIdx.x * blockDim.x + threadIdx.x;     // NL*128*256
    if (idx >= NL * HD * HD2) return;
    int l = idx / (HD * HD2), rem = idx % (HD * HD2);
    int n = rem / HD2, k = rem % HD2;
    float w = W2[((size_t)l * HD2 + k) * HD + n];
    __nv_bfloat16 h = __float2bfloat16(w);
    __nv_bfloat16 lo = __float2bfloat16(w - __bfloat162float(h));
    size_t base = (size_t)l * 2 * HD * HD2;
    g_B2w[base + (size_t)n * HD2 + k] = h;
    g_B2w[base + (size_t)HD * HD2 + (size_t)n * HD2 + k] = lo;
}

// ---------------- atom embedding ------------------------------------------------
__global__ void k_embed(const float* __restrict__ x, const float* __restrict__ W,
                        const float* __restrict__ b) {
    int idx = blockIdx.x * blockDim.x + threadIdx.x;
    if (idx >= NN * HD) return;
    int n = idx >> 7, c = idx & 127;
    const float* xr = x + n * 9;
    float acc = b[c];
#pragma unroll
    for (int k = 0; k < 9; k++) acc = fmaf(xr[k], W[k * HD + c], acc);
    g_h[idx] = acc;
}

// ---------------- GIN aggregation -> z (bf16 hi/lo) ---------------------------
__global__ void k_agg(const float* __restrict__ eps, int l) {
    int wid = (blockIdx.x * blockDim.x + threadIdx.x) >> 5;
    if (wid >= NN) return;
    int lane = threadIdx.x & 31;
    const float4* h4 = (const float4*)g_h;
    float sc = 1.0f + eps[l];
    float4 a = h4[wid * 32 + lane];
    a.x *= sc; a.y *= sc; a.z *= sc; a.w *= sc;
    int j = g_rowptr[wid], e = g_rowptr[wid + 1];
    for (; j + 3 < e; j += 4) {
        int m0 = g_col[j], m1 = g_col[j + 1], m2 = g_col[j + 2], m3 = g_col[j + 3];
        float4 v0 = h4[m0 * 32 + lane], v1 = h4[m1 * 32 + lane];
        float4 v2 = h4[m2 * 32 + lane], v3 = h4[m3 * 32 + lane];
        a.x += v0.x + v1.x + v2.x + v3.x;
        a.y += v0.y + v1.y + v2.y + v3.y;
        a.z += v0.z + v1.z + v2.z + v3.z;
        a.w += v0.w + v1.w + v2.w + v3.w;
    }
    for (; j < e; j++) {
        float4 v = h4[g_col[j] * 32 + lane];
        a.x += v.x; a.y += v.y; a.z += v.z; a.w += v.w;
    }
    float vv[4] = {a.x, a.y, a.z, a.w};
    uint32_t hw[2], lw[2];
#pragma unroll
    for (int p = 0; p < 2; p++) {
        __nv_bfloat16 h0 = __float2bfloat16(vv[2 * p]);
        __nv_bfloat16 h1 = __float2bfloat16(vv[2 * p + 1]);
        __nv_bfloat16 l0 = __float2bfloat16(vv[2 * p] - __bfloat162float(h0));
        __nv_bfloat16 l1 = __float2bfloat16(vv[2 * p + 1] - __bfloat162float(h1));
        hw[p] = (uint32_t)__bfloat16_as_ushort(h0) | ((uint32_t)__bfloat16_as_ushort(h1) << 16);
        lw[p] = (uint32_t)__bfloat16_as_ushort(l0) | ((uint32_t)__bfloat16_as_ushort(l1) << 16);
    }
    ((uint2*)(g_zhi + (size_t)wid * HD))[lane] = make_uint2(hw[0], hw[1]);
    ((uint2*)(g_zlo + (size_t)wid * HD))[lane] = make_uint2(lw[0], lw[1]);
}

// ---------------- HMMA GEMM + BN + ReLU (bf16x3 emulation) ---------------------
// MODE 0: u = relu(BN(z @ W1)), KDIM=128, NOUT=256, out bf16 hi/lo
// MODE 1: h = relu(BN(u @ W2)), KDIM=256, NOUT=128, out fp32
// Persistent CTAs; tile = 64 rows x NOUT. 8 warps: wm = wid&1 (32 rows),
// wn = wid>>1 (NOUT/4 cols). Warp tile 32 x NOUT/4, mma m16n8k16.
template <int KDIM, int NOUT, int MODE>
__global__ void __launch_bounds__(256, 1)
k_gemm_mma(int l, const float* __restrict__ bb, const float* __restrict__ gm,
           const float* __restrict__ bt, const float* __restrict__ mn,
           const float* __restrict__ vr) {
    constexpr int P   = KDIM * 2 + 16;   // smem row pitch (bytes), +16 kills LDSM conflicts
    constexpr int NT  = NOUT / 32;       // n8-tiles per warp
    constexpr int NW  = NOUT / 4;        // warp n-width
    constexpr int KS  = KDIM / 16;       // k-steps
    constexpr int RC  = KDIM / 8;        // uint4 chunks per row
    constexpr int AHI = 0;
    constexpr int ALO = 64 * P;
    constexpr int BHI = 128 * P;
    constexpr int BLO = BHI + NOUT * P;
    constexpr int SAC = BLO + NOUT * P;
    constexpr int SCC = SAC + NOUT * 4;

    extern __shared__ char smem[];
    const uint32_t sb = smem_u32(smem);
    const int tid = threadIdx.x, wid = tid >> 5, lane = tid & 31;
    const int wm = wid & 1, wn = wid >> 1;

    const __nv_bfloat16* in_hi = (MODE == 0) ? g_zhi : g_uhi;
    const __nv_bfloat16* in_lo = (MODE == 0) ? g_zlo : g_ulo;
    const __nv_bfloat16* Bsrc = (MODE == 0)
        ? (g_B1w + (size_t)l * 2 * HD2 * HD)
        : (g_B2w + (size_t)l * 2 * HD * HD2);

    // ---- load B (hi|lo) into smem, BN constants -------------------------------
    for (int c = tid; c < 2 * NOUT * RC; c += 256) {
        int buf = c / (NOUT * RC);
        int rem = c - buf * NOUT * RC;
        int n = rem / RC, q = rem % RC;
        uint4 v = ((const uint4*)Bsrc)[c];
        *(uint4*)(smem + (buf ? BLO : BHI) + n * P + q * 16) = v;
    }
    for (int c = tid; c < NOUT; c += 256) {
        float a = gm[c] * rsqrtf(vr[c] + 1e-5f);
        ((float*)(smem + SAC))[c] = a;
        ((float*)(smem + SCC))[c] = fmaf(a, bb[c] - mn[c], bt[c]);
    }
    __syncthreads();

    const float* Ac = (const float*)(smem + SAC);
    const float* Cc = (const float*)(smem + SCC);
    const uint32_t lrow = (lane & 15), lcol = (lane >> 4) * 16;
    const int tiles = (NN + 63) / 64;

    for (int tile = blockIdx.x; tile < tiles; tile += gridDim.x) {
        const int row0 = tile * 64;
        // ---- stage A tile (hi|lo) -------------------------------------------
        for (int c = tid; c < 2 * 64 * RC; c += 256) {
            int buf = c / (64 * RC);
            int rem = c - buf * 64 * RC;
            int r = rem / RC, q = rem % RC;
            int row = row0 + r;
            const __nv_bfloat16* src = buf ? in_lo : in_hi;
            uint4 v = (row < NN) ? ((const uint4*)(src + (size_t)row * KDIM))[q]
                                 : make_uint4(0, 0, 0, 0);
            *(uint4*)(smem + (buf ? ALO : AHI) + r * P + q * 16) = v;
        }
        __syncthreads();

        float acc[2][NT][4];
#pragma unroll
        for (int i = 0; i < 2; i++)
#pragma unroll
            for (int j = 0; j < NT; j++)
#pragma unroll
                for (int q = 0; q < 4; q++) acc[i][j][q] = 0.f;

#pragma unroll
        for (int ks = 0; ks < KS; ks++) {
            uint32_t ah[2][4], al[2][4];
#pragma unroll
            for (int i = 0; i < 2; i++) {
                uint32_t aAddr = sb + AHI + (wm * 32 + i * 16 + lrow) * P + ks * 32 + lcol;
                LDSM4(ah[i], aAddr);
                LDSM4(al[i], aAddr + (ALO - AHI));
            }
#pragma unroll
            for (int np = 0; np < NT / 2; np++) {
                int n0 = wn * NW + np * 16;
                uint32_t bAddr = sb + BHI + (n0 + lrow) * P + ks * 32 + lcol;
                uint32_t bh[4], bl[4];
                LDSM4(bh, bAddr);
                LDSM4(bl, bAddr + (BLO - BHI));
#pragma unroll
                for (int i = 0; i < 2; i++) {
                    MMA16816(acc[i][2 * np],     ah[i], bh[0], bh[2]);
                    MMA16816(acc[i][2 * np],     ah[i], bl[0], bl[2]);
                    MMA16816(acc[i][2 * np],     al[i], bh[0], bh[2]);
                    MMA16816(acc[i][2 * np + 1], ah[i], bh[1], bh[3]);
                    MMA16816(acc[i][2 * np + 1], ah[i], bl[1], bl[3]);
                    MMA16816(acc[i][2 * np + 1], al[i], bh[1], bh[3]);
                }
            }
        }

        // ---- epilogue: BN + ReLU, direct gmem store ---------------------------
#pragma unroll
        for (int i = 0; i < 2; i++) {
#pragma unroll
            for (int j = 0; j < NT; j++) {
                int r0 = row0 + wm * 32 + i * 16 + (lane >> 2);
                int r1 = r0 + 8;
                int c = wn * NW + j * 8 + (lane & 3) * 2;
                float a0 = Ac[c], a1 = Ac[c + 1], c0 = Cc[c], c1 = Cc[c + 1];
                float y00 = fmaxf(fmaf(acc[i][j][0], a0, c0), 0.f);
                float y01 = fmaxf(fmaf(acc[i][j][1], a1, c1), 0.f);
                float y10 = fmaxf(fmaf(acc[i][j][2], a0, c0), 0.f);
                float y11 = fmaxf(fmaf(acc[i][j][3], a1, c1), 0.f);
                if (MODE == 0) {
                    if (r0 < NN) {
                        __nv_bfloat16 h0 = __float2bfloat16(y00), h1 = __float2bfloat16(y01);
                        uint32_t hw = (uint32_t)__bfloat16_as_ushort(h0) | ((uint32_t)__bfloat16_as_ushort(h1) << 16);
                        __nv_bfloat16 l0 = __float2bfloat16(y00 - __bfloat162float(h0));
                        __nv_bfloat16 l1 = __float2bfloat16(y01 - __bfloat162float(h1));
                        uint32_t lw = (uint32_t)__bfloat16_as_ushort(l0) | ((uint32_t)__bfloat16_as_ushort(l1) << 16);
                        *(uint32_t*)(g_uhi + (size_t)r0 * HD2 + c) = hw;
                        *(uint32_t*)(g_ulo + (size_t)r0 * HD2 + c) = lw;
                    }
                    if (r1 < NN) {
                        __nv_bfloat16 h0 = __float2bfloat16(y10), h1 = __float2bfloat16(y11);
                        uint32_t hw = (uint32_t)__bfloat16_as_ushort(h0) | ((uint32_t)__bfloat16_as_ushort(h1) << 16);
                        __nv_bfloat16 l0 = __float2bfloat16(y10 - __bfloat162float(h0));
                        __nv_bfloat16 l1 = __float2bfloat16(y11 - __bfloat162float(h1));
                        uint32_t lw = (uint32_t)__bfloat16_as_ushort(l0) | ((uint32_t)__bfloat16_as_ushort(l1) << 16);
                        *(uint32_t*)(g_uhi + (size_t)r1 * HD2 + c) = hw;
                        *(uint32_t*)(g_ulo + (size_t)r1 * HD2 + c) = lw;
                    }
                } else {
                    if (r0 < NN) *(float2*)(g_h + (size_t)r0 * HD + c) = make_float2(y00, y01);
                    if (r1 < NN) *(float2*)(g_h + (size_t)r1 * HD + c) = make_float2(y10, y11);
                }
            }
        }
        __syncthreads();
    }
}

// ---------------- global mean pool --------------------------------------------
__global__ void k_pool(const int* __restrict__ batch, float* __restrict__ out) {
    int g = blockIdx.x, c = threadIdx.x;
    int lo = 0, hi = NN;
    while (lo < hi) { int mid = (lo + hi) >> 1; if (batch[mid] < g) lo = mid + 1; else hi = mid; }
    int start = lo;
    lo = start; hi = NN;
    while (lo < hi) { int mid = (lo + hi) >> 1; if (batch[mid] < g + 1) lo = mid + 1; else hi = mid; }
    int end = lo;
    float acc = 0.f;
    int n = start;
    for (; n + 3 < end; n += 4) {
        acc += g_h[(n + 0) * HD + c];
        acc += g_h[(n + 1) * HD + c];
        acc += g_h[(n + 2) * HD + c];
        acc += g_h[(n + 3) * HD + c];
    }
    for (; n < end; n++) acc += g_h[n * HD + c];
    float cnt = (float)(end - start);
    out[g * HD + c] = acc / fmaxf(cnt, 1.f);
}

// ---------------- launch --------------------------------------------------------
extern "C" void kernel_launch(void* const* d_in, const int* in_sizes, int n_in,
                              void* d_out, int out_size) {
    const float* x    = (const float*)d_in[0];
    const int*   ei   = (const int*)d_in[1];
    const int*   bat  = (const int*)d_in[2];
    const float* Wemb = (const float*)d_in[3];
    const float* bemb = (const float*)d_in[4];
    const float* eps  = (const float*)d_in[5];
    const float* W1   = (const float*)d_in[6];
    const float* b1   = (const float*)d_in[7];
    const float* g1   = (const float*)d_in[8];
    const float* be1  = (const float*)d_in[9];
    const float* m1   = (const float*)d_in[10];
    const float* v1   = (const float*)d_in[11];
    const float* W2   = (const float*)d_in[12];
    const float* b2   = (const float*)d_in[13];
    const float* g2   = (const float*)d_in[14];
    const float* be2  = (const float*)d_in[15];
    const float* m2   = (const float*)d_in[16];
    const float* v2   = (const float*)d_in[17];
    float* out = (float*)d_out;

    // smem totals: MODE0 = 176128 B, MODE1 = 203776 B
    cudaFuncSetAttribute(k_gemm_mma<128, 256, 0>, cudaFuncAttributeMaxDynamicSharedMemorySize, 176128);
    cudaFuncSetAttribute(k_gemm_mma<256, 128, 1>, cudaFuncAttributeMaxDynamicSharedMemorySize, 203776);

    // CSR build + weight packing (once per launch)
    k_zero_deg<<<(NN + 255) / 256, 256>>>();
    k_hist<<<(NE + 255) / 256, 256>>>(ei);
    k_scan1<<<SCAN_NB, 1024>>>();
    k_scan2<<<1, 128>>>();
    k_finalize<<<(NN + 255) / 256, 256>>>();
    k_scatter<<<(NE + 255) / 256, 256>>>(ei);
    k_packW1<<<(NL * HD2 * HD + 255) / 256, 256>>>(W1);
    k_packW2<<<(NL * HD * HD2 + 255) / 256, 256>>>(W2);

    k_embed<<<(NN * HD + 255) / 256, 256>>>(x, Wemb, bemb);

    for (int l = 0; l < NL; l++) {
        k_agg<<<(NN + 7) / 8, 256>>>(eps, l);
        k_gemm_mma<128, 256, 0><<<148, 256, 176128>>>(l, b1 + l * HD2, g1 + l * HD2,
                                                      be1 + l * HD2, m1 + l * HD2, v1 + l * HD2);
        k_gemm_mma<256, 128, 1><<<148, 256, 203776>>>(l, b2 + l * HD, g2 + l * HD,
                                                      be2 + l * HD, m2 + l * HD, v2 + l * HD);
    }

    k_pool<<<NG, 128>>>(bat, out);
}